// round 5
// baseline (speedup 1.0000x reference)
#include <cuda_runtime.h>
#include <cstdint>

#define D_FEAT   128
#define DV       32            // float4 per row
#define NMAX     100352        // >= N_NODES, padded
#define EMAX     1600000
#define SCAN_T   1024          // scan tile

// ---- scratch: __device__ globals (no allocation allowed) ----
__device__ int   g_idx64;          // 1 if indices are int64, 0 if int32
__device__ int   g_src32[EMAX];
__device__ int   g_dst32[EMAX];
__device__ int   g_deg_out[NMAX];
__device__ int   g_deg_in[NMAX];
__device__ float g_rdeg[NMAX];
__device__ int   g_row_start[NMAX + 1];
__device__ int   g_cursor[NMAX];
__device__ int   g_blk_sums[SCAN_T];
__device__ int   g_esrc[EMAX];
__device__ float g_enorm[EMAX];

// ---------------------------------------------------------------------------
// Detect index dtype. If int64 (values < 2^31), every odd 32-bit word is 0.
// If int32, odd words are random node ids, virtually never all zero.
__global__ void detect_kernel(const unsigned int* __restrict__ raw, int n_words) {
    __shared__ int any;
    if (threadIdx.x == 0) any = 0;
    __syncthreads();
    int acc = 0;
    for (int i = threadIdx.x; i < n_words / 2; i += blockDim.x)
        acc |= (raw[2 * i + 1] != 0u);
    if (acc) atomicOr(&any, 1);
    __syncthreads();
    if (threadIdx.x == 0) g_idx64 = (any == 0);   // odd words all zero -> int64
}

// Normalize both index arrays to int32 (also zero-init degree arrays here).
__global__ void convert_kernel(const void* __restrict__ src,
                               const void* __restrict__ dst,
                               int n_edges, int n_nodes) {
    int e = blockIdx.x * blockDim.x + threadIdx.x;
    int is64 = g_idx64;
    if (e < n_edges) {
        if (is64) {
            g_src32[e] = (int)((const long long*)src)[e];
            g_dst32[e] = (int)((const long long*)dst)[e];
        } else {
            g_src32[e] = ((const int*)src)[e];
            g_dst32[e] = ((const int*)dst)[e];
        }
    }
    if (e < n_nodes) { g_deg_out[e] = 0; g_deg_in[e] = 0; }
}

__global__ void hist_kernel(int n_edges) {
    int e = blockIdx.x * blockDim.x + threadIdx.x;
    if (e < n_edges) {
        atomicAdd(&g_deg_out[g_src32[e]], 1);
        atomicAdd(&g_deg_in[g_dst32[e]], 1);
    }
}

__global__ void rdeg_kernel(int n_nodes) {
    int i = blockIdx.x * blockDim.x + threadIdx.x;
    if (i < n_nodes) {
        int d = g_deg_out[i];
        g_rdeg[i] = rsqrtf((float)(d > 0 ? d : 1));
    }
}

// ---- 3-phase exclusive scan of g_deg_in -> g_row_start --------------------
__global__ void scan1_kernel(int n_nodes) {
    __shared__ int sh[2][SCAN_T];
    int t = threadIdx.x;
    int i = blockIdx.x * SCAN_T + t;
    int v = (i < n_nodes) ? g_deg_in[i] : 0;
    int pi = 0;
    sh[0][t] = v;
    __syncthreads();
    #pragma unroll
    for (int off = 1; off < SCAN_T; off <<= 1) {
        int nv = sh[pi][t];
        if (t >= off) nv += sh[pi][t - off];
        sh[pi ^ 1][t] = nv;
        pi ^= 1;
        __syncthreads();
    }
    int incl = sh[pi][t];
    if (i < n_nodes) g_row_start[i] = incl - v;   // exclusive
    if (t == SCAN_T - 1) g_blk_sums[blockIdx.x] = incl;
}

__global__ void scan2_kernel(int n_blocks) {
    __shared__ int sh[2][SCAN_T];
    int t = threadIdx.x;
    int v = (t < n_blocks) ? g_blk_sums[t] : 0;
    int pi = 0;
    sh[0][t] = v;
    __syncthreads();
    #pragma unroll
    for (int off = 1; off < SCAN_T; off <<= 1) {
        int nv = sh[pi][t];
        if (t >= off) nv += sh[pi][t - off];
        sh[pi ^ 1][t] = nv;
        pi ^= 1;
        __syncthreads();
    }
    if (t < n_blocks) g_blk_sums[t] = sh[pi][t] - v;  // exclusive
}

__global__ void scan3_kernel(int n_nodes, int n_edges) {
    int i = blockIdx.x * blockDim.x + threadIdx.x;
    if (i < n_nodes) {
        int r = g_row_start[i] + g_blk_sums[i / SCAN_T];
        g_row_start[i] = r;
        g_cursor[i]    = r;
    }
    if (i == 0) g_row_start[n_nodes] = n_edges;
}

// ---- bucket edges by dst; precompute per-edge norm ------------------------
__global__ void bucket_kernel(int n_edges) {
    int e = blockIdx.x * blockDim.x + threadIdx.x;
    if (e < n_edges) {
        int s = g_src32[e];
        int d = g_dst32[e];
        int pos = atomicAdd(&g_cursor[d], 1);
        g_esrc[pos]  = s;
        g_enorm[pos] = g_rdeg[s] * g_rdeg[d];
    }
}

// ---- gather: one warp per dst node, register accumulation -----------------
__global__ __launch_bounds__(256) void gather_kernel(
    const float4* __restrict__ x, float4* __restrict__ out, int n_nodes)
{
    int warp = (blockIdx.x * blockDim.x + threadIdx.x) >> 5;
    int lane = threadIdx.x & 31;
    if (warp >= n_nodes) return;

    int beg = g_row_start[warp];
    int end = g_row_start[warp + 1];

    float4 acc = make_float4(0.f, 0.f, 0.f, 0.f);

    int e = beg;
    while (e < end) {
        int m = min(32, end - e);
        int   sv = 0;
        float nv = 0.f;
        if (lane < m) {                     // coalesced edge-meta loads
            sv = g_esrc[e + lane];
            nv = g_enorm[e + lane];
        }
        #pragma unroll 4
        for (int j = 0; j < m; j++) {
            int   sj = __shfl_sync(0xffffffffu, sv, j);
            float nj = __shfl_sync(0xffffffffu, nv, j);
            float4 v = x[(size_t)sj * DV + lane];
            acc.x += v.x * nj;
            acc.y += v.y * nj;
            acc.z += v.z * nj;
            acc.w += v.w * nj;
        }
        e += m;
    }
    out[(size_t)warp * DV + lane] = acc;    // every row written -> no memset
}

// ---------------------------------------------------------------------------
extern "C" void kernel_launch(void* const* d_in, const int* in_sizes, int n_in,
                              void* d_out, int out_size)
{
    const float* x   = (const float*)d_in[0];
    const void*  src = d_in[1];
    const void*  dst = d_in[2];
    float*       out = (float*)d_out;

    int n_nodes = in_sizes[0] / D_FEAT;
    int n_edges = in_sizes[1];
    int scan_blocks = (n_nodes + SCAN_T - 1) / SCAN_T;   // 98 for 100K

    // Probe 2048 int32 words (8KB) — safe for both int32 (6.4MB) and int64 buffers.
    int probe_words = 2048 < n_edges ? 2048 : n_edges;
    detect_kernel<<<1, 256>>>((const unsigned int*)src, probe_words);

    int ethreads = (n_edges > n_nodes ? n_edges : n_nodes);
    convert_kernel<<<(ethreads + 255) / 256, 256>>>(src, dst, n_edges, n_nodes);

    hist_kernel<<<(n_edges + 255) / 256, 256>>>(n_edges);
    rdeg_kernel<<<(n_nodes + 255) / 256, 256>>>(n_nodes);

    scan1_kernel<<<scan_blocks, SCAN_T>>>(n_nodes);
    scan2_kernel<<<1, SCAN_T>>>(scan_blocks);
    scan3_kernel<<<(n_nodes + 255) / 256, 256>>>(n_nodes, n_edges);

    bucket_kernel<<<(n_edges + 255) / 256, 256>>>(n_edges);

    long long total_threads = (long long)n_nodes * 32;
    gather_kernel<<<(int)((total_threads + 255) / 256), 256>>>(
        (const float4*)x, (float4*)out, n_nodes);

    (void)n_in; (void)out_size;
}

// round 6
// speedup vs baseline: 1.0823x; 1.0823x over previous
#include <cuda_runtime.h>
#include <cstdint>

#define D_FEAT   128
#define DV       32            // float4 per row
#define NMAX     100352        // >= N_NODES, padded
#define EMAX     1600000
#define SCAN_T   1024          // scan tile

// ---- scratch: __device__ globals (no allocation allowed) ----
__device__ int                g_idx64;       // 1 if indices are int64
__device__ int                g_src32[EMAX];
__device__ int                g_dst32[EMAX];
__device__ unsigned long long g_epack[EMAX]; // {norm_bits:32 | src:32}
__device__ int                g_deg_out[NMAX];
__device__ int                g_deg_in[NMAX];
__device__ float              g_rdeg[NMAX];
__device__ int                g_row_start[NMAX + 1];
__device__ int                g_cursor[NMAX];
__device__ int                g_blk_sums[SCAN_T];

// ---------------------------------------------------------------------------
// Zero degree arrays; block 0 additionally probes the index dtype.
// int64 little-endian with values < 2^31 -> every odd 32-bit word is 0.
__global__ void zero_detect_kernel(const unsigned int* __restrict__ raw,
                                   int n_words, int n_nodes) {
    int i = blockIdx.x * blockDim.x + threadIdx.x;
    if (i < n_nodes) { g_deg_out[i] = 0; g_deg_in[i] = 0; }
    if (blockIdx.x == 0) {
        __shared__ int any;
        if (threadIdx.x == 0) any = 0;
        __syncthreads();
        int acc = 0;
        for (int w = threadIdx.x; w < n_words / 2; w += blockDim.x)
            acc |= (raw[2 * w + 1] != 0u);
        if (acc) atomicOr(&any, 1);
        __syncthreads();
        if (threadIdx.x == 0) g_idx64 = (any == 0);
    }
}

// Convert indices to int32 scratch AND build both degree histograms in one pass.
__global__ void convhist_kernel(const void* __restrict__ src,
                                const void* __restrict__ dst, int n_edges) {
    int e = blockIdx.x * blockDim.x + threadIdx.x;
    if (e >= n_edges) return;
    int s, d;
    if (g_idx64) {
        s = (int)((const long long*)src)[e];
        d = (int)((const long long*)dst)[e];
    } else {
        s = ((const int*)src)[e];
        d = ((const int*)dst)[e];
    }
    g_src32[e] = s;
    g_dst32[e] = d;
    atomicAdd(&g_deg_out[s], 1);
    atomicAdd(&g_deg_in[d], 1);
}

// ---- 3-phase exclusive scan of g_deg_in -> g_row_start --------------------
__global__ void scan1_kernel(int n_nodes) {
    __shared__ int sh[2][SCAN_T];
    int t = threadIdx.x;
    int i = blockIdx.x * SCAN_T + t;
    int v = (i < n_nodes) ? g_deg_in[i] : 0;
    int pi = 0;
    sh[0][t] = v;
    __syncthreads();
    #pragma unroll
    for (int off = 1; off < SCAN_T; off <<= 1) {
        int nv = sh[pi][t];
        if (t >= off) nv += sh[pi][t - off];
        sh[pi ^ 1][t] = nv;
        pi ^= 1;
        __syncthreads();
    }
    int incl = sh[pi][t];
    if (i < n_nodes) g_row_start[i] = incl - v;   // exclusive
    if (t == SCAN_T - 1) g_blk_sums[blockIdx.x] = incl;
}

__global__ void scan2_kernel(int n_blocks) {
    __shared__ int sh[2][SCAN_T];
    int t = threadIdx.x;
    int v = (t < n_blocks) ? g_blk_sums[t] : 0;
    int pi = 0;
    sh[0][t] = v;
    __syncthreads();
    #pragma unroll
    for (int off = 1; off < SCAN_T; off <<= 1) {
        int nv = sh[pi][t];
        if (t >= off) nv += sh[pi][t - off];
        sh[pi ^ 1][t] = nv;
        pi ^= 1;
        __syncthreads();
    }
    if (t < n_blocks) g_blk_sums[t] = sh[pi][t] - v;  // exclusive
}

// Finalize CSR offsets + cursors; also compute rdeg = rsqrt(max(deg_out,1)).
__global__ void scan3_kernel(int n_nodes, int n_edges) {
    int i = blockIdx.x * blockDim.x + threadIdx.x;
    if (i < n_nodes) {
        int r = g_row_start[i] + g_blk_sums[i / SCAN_T];
        g_row_start[i] = r;
        g_cursor[i]    = r;
        int dg = g_deg_out[i];
        g_rdeg[i] = rsqrtf((float)(dg > 0 ? dg : 1));
    }
    if (i == 0) g_row_start[n_nodes] = n_edges;
}

// ---- bucket edges by dst; single 8B scatter of packed {norm, src} ---------
__global__ void bucket_kernel(int n_edges) {
    int e = blockIdx.x * blockDim.x + threadIdx.x;
    if (e >= n_edges) return;
    int s = g_src32[e];
    int d = g_dst32[e];
    float norm = g_rdeg[s] * g_rdeg[d];
    int pos = atomicAdd(&g_cursor[d], 1);
    g_epack[pos] = (unsigned long long)(unsigned)s
                 | ((unsigned long long)__float_as_uint(norm) << 32);
}

// ---- gather: one warp per dst node, register accumulation -----------------
__global__ __launch_bounds__(256) void gather_kernel(
    const float4* __restrict__ x, float4* __restrict__ out, int n_nodes)
{
    int warp = (blockIdx.x * blockDim.x + threadIdx.x) >> 5;
    int lane = threadIdx.x & 31;
    if (warp >= n_nodes) return;

    int beg = g_row_start[warp];
    int end = g_row_start[warp + 1];

    float4 acc = make_float4(0.f, 0.f, 0.f, 0.f);

    for (int e = beg; e < end; e += 32) {
        int m = min(32, end - e);
        unsigned long long pv = 0ull;
        if (lane < m) pv = g_epack[e + lane];       // one coalesced 8B load
        int   sv = (int)(unsigned)pv;
        float nv = __uint_as_float((unsigned)(pv >> 32));
        #pragma unroll 8
        for (int j = 0; j < m; j++) {
            int   sj = __shfl_sync(0xffffffffu, sv, j);
            float nj = __shfl_sync(0xffffffffu, nv, j);
            float4 v = x[(size_t)sj * DV + lane];
            acc.x += v.x * nj;
            acc.y += v.y * nj;
            acc.z += v.z * nj;
            acc.w += v.w * nj;
        }
    }
    out[(size_t)warp * DV + lane] = acc;    // every row written -> no memset
}

// ---------------------------------------------------------------------------
extern "C" void kernel_launch(void* const* d_in, const int* in_sizes, int n_in,
                              void* d_out, int out_size)
{
    const float* x   = (const float*)d_in[0];
    const void*  src = d_in[1];
    const void*  dst = d_in[2];
    float*       out = (float*)d_out;

    int n_nodes = in_sizes[0] / D_FEAT;
    int n_edges = in_sizes[1];
    int scan_blocks = (n_nodes + SCAN_T - 1) / SCAN_T;   // 98 for 100K

    int probe_words = 2048 < n_edges ? 2048 : n_edges;   // 8KB probe, safe both ways

    zero_detect_kernel<<<(n_nodes + 255) / 256, 256>>>(
        (const unsigned int*)src, probe_words, n_nodes);

    convhist_kernel<<<(n_edges + 255) / 256, 256>>>(src, dst, n_edges);

    scan1_kernel<<<scan_blocks, SCAN_T>>>(n_nodes);
    scan2_kernel<<<1, SCAN_T>>>(scan_blocks);
    scan3_kernel<<<(n_nodes + 255) / 256, 256>>>(n_nodes, n_edges);

    bucket_kernel<<<(n_edges + 255) / 256, 256>>>(n_edges);

    long long total_threads = (long long)n_nodes * 32;
    gather_kernel<<<(int)((total_threads + 255) / 256), 256>>>(
        (const float4*)x, (float4*)out, n_nodes);

    (void)n_in; (void)out_size;
}